// round 6
// baseline (speedup 1.0000x reference)
#include <cuda_runtime.h>
#include <cuda_bf16.h>
#include <math.h>

// ---------------- problem constants ----------------
#define BATCH     16
#define SEQLEN    4096
#define INPUT_DIM 57
#define D_MODEL   256
#define D_INNER   512
#define D_STATE   8
#define HEADDIM   16
#define NHEADS    32
#define CHUNKSZ   8
#define CONV_DIM  528          // D_INNER + 2*D_STATE
#define D_INPROJ  1072         // 2*D_INNER + 2*D_STATE + NHEADS
#define OUT_SIZE  6
#define NC        (SEQLEN/CHUNKSZ)   // 512 chunks per sequence
#define NSEG      16
#define CPS       (NC/NSEG)          // 32 chunks per segment
#define NTOK      (BATCH*SEQLEN)     // 65536
#define FULLM     0xffffffffu

// ---------------- scratch (device globals; no allocations) ----------------
__device__ __align__(16) float g_Wc  [D_INPROJ*INPUT_DIM];
__device__ __align__(16) float g_bias[D_INPROJ];
__device__ __align__(16) float g_zx  [NTOK*D_INPROJ];      // in-proj output (z | xBC | dt)
__device__ __align__(16) __nv_bfloat16 g_S[(size_t)BATCH*NHEADS*NC*128]; // chunk state contribs
__device__ __align__(16) __nv_bfloat16 g_G[(size_t)BATCH*NHEADS*NC*128]; // chunk gated-C matrices
__device__ __align__(16) float g_d   [BATCH*NHEADS*NC];                  // chunk decays
__device__ __align__(16) float g_Sfin[BATCH*NHEADS*NSEG*HEADDIM*D_STATE];
__device__ __align__(16) float g_Dseg[BATCH*NHEADS*NSEG];
__device__ __align__(16) float g_hin [BATCH*NHEADS*NSEG*HEADDIM*D_STATE];
__device__ __align__(16) float g_ybar[BATCH*D_INNER];

// ---------------- helpers ----------------
__device__ __forceinline__ float siluf_fast(float x) {
    return x * __frcp_rn(1.f + __expf(-x));
}
__device__ __forceinline__ unsigned long long f2pack(float lo, float hi) {
    unsigned long long r;
    asm("mov.b64 %0, {%1,%2};" : "=l"(r) : "f"(lo), "f"(hi));
    return r;
}
__device__ __forceinline__ void f2unpack(unsigned long long v, float& lo, float& hi) {
    asm("mov.b64 {%0,%1}, %2;" : "=f"(lo), "=f"(hi) : "l"(v));
}
__device__ __forceinline__ unsigned long long ffma2(unsigned long long a, unsigned long long b, unsigned long long c) {
    unsigned long long d;
    asm("fma.rn.f32x2 %0, %1, %2, %3;" : "=l"(d) : "l"(a), "l"(b), "l"(c));
    return d;
}
__device__ __forceinline__ unsigned short bf_enc(float x) {
    return __bfloat16_as_ushort(__float2bfloat16_rn(x));
}
__device__ __forceinline__ float bf_dec(unsigned short u) {
    return __bfloat162float(__ushort_as_bfloat16(u));
}

// ---------------- K1: W_comb = W_inproj @ W_in, bias = W_inproj @ b_in ----------------
__global__ void k_wcomb(const float* __restrict__ Wip, const float* __restrict__ Win,
                        const float* __restrict__ bin) {
    int idx = blockIdx.x * 256 + threadIdx.x;
    if (idx < D_INPROJ * INPUT_DIM) {
        int r = idx / INPUT_DIM, k = idx % INPUT_DIM;
        float s = 0.f;
        #pragma unroll 8
        for (int m = 0; m < D_MODEL; m++) s += Wip[r * D_MODEL + m] * Win[m * INPUT_DIM + k];
        g_Wc[idx] = s;
    } else if (idx < D_INPROJ * INPUT_DIM + D_INPROJ) {
        int r = idx - D_INPROJ * INPUT_DIM;
        float s = 0.f;
        #pragma unroll 8
        for (int m = 0; m < D_MODEL; m++) s += Wip[r * D_MODEL + m] * bin[m];
        g_bias[r] = s;
    }
}

// ---------------- K2: zxbcdt = x @ W_comb^T + bias  (M=65536, N=1072, K=57) ----------------
// BM=128 rows, BN=64 cols, 256 threads, thread tile 8x4 (rows paired for f32x2).
#define ASTRIDE 140   // padded row stride for transposed A (mult of 4, low bank conflict)
#define BSTRIDE 68
__global__ __launch_bounds__(256) void k_gemm(const float* __restrict__ x) {
    __shared__ __align__(16) float Ast[INPUT_DIM * ASTRIDE];  // [k][row]
    __shared__ __align__(16) float Bs [INPUT_DIM * BSTRIDE];  // [k][col]
    const int tid = threadIdx.x;
    const int tx = tid & 15, ty = tid >> 4;     // tx: col group (4 cols), ty: row group (8 rows)
    const int m0 = blockIdx.x * 128;
    const int n0 = blockIdx.y * 64;

    for (int idx = tid; idx < 128 * INPUT_DIM; idx += 256) {
        int r = idx / INPUT_DIM, k = idx - r * INPUT_DIM;
        Ast[k * ASTRIDE + r] = x[(size_t)(m0 + r) * INPUT_DIM + k];
    }
    for (int idx = tid; idx < 64 * INPUT_DIM; idx += 256) {
        int c = idx / INPUT_DIM, k = idx - c * INPUT_DIM;
        int col = n0 + c;
        Bs[k * BSTRIDE + c] = (col < D_INPROJ) ? g_Wc[col * INPUT_DIM + k] : 0.f;
    }
    __syncthreads();

    unsigned long long acc[4][4];   // [row-pair][col]
    #pragma unroll
    for (int rp = 0; rp < 4; rp++)
        #pragma unroll
        for (int c = 0; c < 4; c++) acc[rp][c] = 0ull;

    #pragma unroll 3
    for (int k = 0; k < INPUT_DIM; k++) {
        const float4 a03 = *reinterpret_cast<const float4*>(&Ast[k * ASTRIDE + ty * 8]);
        const float4 a47 = *reinterpret_cast<const float4*>(&Ast[k * ASTRIDE + ty * 8 + 4]);
        const float4 bv  = *reinterpret_cast<const float4*>(&Bs [k * BSTRIDE + tx * 4]);
        unsigned long long pa[4];
        pa[0] = f2pack(a03.x, a03.y); pa[1] = f2pack(a03.z, a03.w);
        pa[2] = f2pack(a47.x, a47.y); pa[3] = f2pack(a47.z, a47.w);
        unsigned long long bd[4];
        bd[0] = f2pack(bv.x, bv.x); bd[1] = f2pack(bv.y, bv.y);
        bd[2] = f2pack(bv.z, bv.z); bd[3] = f2pack(bv.w, bv.w);
        #pragma unroll
        for (int c = 0; c < 4; c++)
            #pragma unroll
            for (int rp = 0; rp < 4; rp++)
                acc[rp][c] = ffma2(pa[rp], bd[c], acc[rp][c]);
    }

    const int colbase = n0 + tx * 4;
    if (colbase < D_INPROJ) {
        const float4 bi = *reinterpret_cast<const float4*>(&g_bias[colbase]);
        #pragma unroll
        for (int rp = 0; rp < 4; rp++) {
            float l0, h0, l1, h1, l2, h2, l3, h3;
            f2unpack(acc[rp][0], l0, h0); f2unpack(acc[rp][1], l1, h1);
            f2unpack(acc[rp][2], l2, h2); f2unpack(acc[rp][3], l3, h3);
            int r0 = m0 + ty * 8 + rp * 2;
            float* p0 = &g_zx[(size_t)r0 * D_INPROJ + colbase];
            *reinterpret_cast<float4*>(p0) =
                make_float4(l0 + bi.x, l1 + bi.y, l2 + bi.z, l3 + bi.w);
            *reinterpret_cast<float4*>(p0 + D_INPROJ) =
                make_float4(h0 + bi.x, h1 + bi.y, h2 + bi.z, h3 + bi.w);
        }
    }
}

// ---------------- K3: zero ybar accumulator ----------------
__global__ void k_zero() { g_ybar[blockIdx.x * D_INNER + threadIdx.x] = 0.f; }

// ---------------- K4: pass A — per-chunk: conv+silu, intra-gated output, S/G/d summaries ----------------
#define CONVP 532   // padded row stride for conv smem
__global__ __launch_bounds__(256) void k_passA(const float* __restrict__ cw, const float* __restrict__ cb,
                                               const float* __restrict__ dtb, const float* __restrict__ Alog,
                                               const float* __restrict__ Dp) {
    __shared__ __align__(16) float s_conv[8 * CONVP];   // conv+silu output: [token][channel]
    __shared__ float s_dt[8][33];                       // raw dt: [token][head]
    __shared__ float s_CB[64];                          // C_i . B_j (head-independent)
    __shared__ float s_sz[8][8][20];                    // silu(z): [warp][token][p]

    const int tid = threadIdx.x, w = tid >> 5, lane = tid & 31;
    const int blk = blockIdx.x;
    const int b = blk >> 9, c = blk & 511;
    const int t0 = c * CHUNKSZ;
    const size_t base = (size_t)(b * SEQLEN + t0) * D_INPROJ;

    // dt tile (coalesced): 8 tokens x 32 heads
    {
        int j = tid >> 5, hh2 = tid & 31;
        s_dt[j][hh2] = g_zx[base + (size_t)j * D_INPROJ + (D_INNER + CONV_DIM) + hh2];
    }

    // depthwise causal conv (width 4) + silu into smem
    for (int ch = tid; ch < CONV_DIM; ch += 256) {
        const float w0 = cw[ch * 4], w1 = cw[ch * 4 + 1], w2 = cw[ch * 4 + 2], w3 = cw[ch * 4 + 3];
        const float bb = cb[ch];
        float v[11];
        #pragma unroll
        for (int tt = 0; tt < 11; tt++) {
            int t = t0 + tt - 3;
            v[tt] = (t >= 0) ? g_zx[(size_t)(b * SEQLEN + t) * D_INPROJ + D_INNER + ch] : 0.f;
        }
        #pragma unroll
        for (int u = 0; u < 8; u++) {
            float s = bb + w0 * v[u] + w1 * v[u + 1] + w2 * v[u + 2] + w3 * v[u + 3];
            s_conv[u * CONVP + ch] = siluf_fast(s);
        }
    }
    __syncthreads();

    // CB[i][j] = C_i . B_j  (shared across all 32 heads)
    if (tid < 64) {
        int i = tid >> 3, j = tid & 7;
        float s = 0.f;
        #pragma unroll
        for (int n = 0; n < 8; n++)
            s += s_conv[i * CONVP + 520 + n] * s_conv[j * CONVP + 512 + n];
        s_CB[tid] = s;
    }
    __syncthreads();

    const int i_ = lane >> 2, q = lane & 3;         // part-1 map
    const int p2 = lane >> 1, n0 = (lane & 1) * 4;  // part-2 map

    #pragma unroll 1
    for (int hh = 0; hh < 4; hh++) {
        const int h = w * 4 + hh;
        const float A = -__expf(Alog[h]);
        const float Dh = Dp[h];

        // dtc + cumulative A on lanes 0..7
        float dtc_l = 0.f;
        if (lane < 8) {
            float xv = s_dt[lane][h] + dtb[h];
            dtc_l = (xv > 20.f) ? xv : __logf(1.f + __expf(xv));
        }
        float cs = dtc_l;
        #pragma unroll
        for (int off = 1; off < 8; off <<= 1) {
            float vv = __shfl_up_sync(FULLM, cs, off);
            if (lane >= off) cs += vv;
        }
        const float cA_l = cs * A;
        const float e_l = __expf(cA_l);                              // exp(cA_j) on lanes<8
        const float cA7 = __shfl_sync(FULLM, cA_l, 7);
        const float coef_l = __expf(cA7 - cA_l) * dtc_l;             // lanes<8

        float e[8], coef[8];
        #pragma unroll
        for (int j = 0; j < 8; j++) {
            e[j]    = __shfl_sync(FULLM, e_l, j);
            coef[j] = __shfl_sync(FULLM, coef_l, j);
        }

        // score factors: 2 exps per lane, gathered via quad shuffles
        const float ca_i  = __shfl_sync(FULLM, cA_l, i_);
        const float ca_q  = __shfl_sync(FULLM, cA_l, q);
        const float ca_q4 = __shfl_sync(FULLM, cA_l, q + 4);
        const float dt_q  = __shfl_sync(FULLM, dtc_l, q);
        const float dt_q4 = __shfl_sync(FULLM, dtc_l, q + 4);
        const float ev0 = __expf(ca_i - ca_q)  * dt_q;    // j = q
        const float ev1 = __expf(ca_i - ca_q4) * dt_q4;   // j = q+4 (may be inf; masked)

        float sc[8];
        #pragma unroll
        for (int j = 0; j < 8; j++) {
            float sj = __shfl_sync(FULLM, (j < 4) ? ev0 : ev1, (i_ << 2) | (j & 3));
            sc[j] = (j <= i_) ? s_CB[i_ * 8 + j] * sj : 0.f;
        }

        // ---- part 1: intra + D term, gated ----
        float4 zq = *reinterpret_cast<const float4*>(&g_zx[base + (size_t)i_ * D_INPROJ + h * 16 + q * 4]);
        float sz0 = siluf_fast(zq.x), sz1 = siluf_fast(zq.y), sz2 = siluf_fast(zq.z), sz3 = siluf_fast(zq.w);
        s_sz[w][i_][q * 4 + 0] = sz0; s_sz[w][i_][q * 4 + 1] = sz1;
        s_sz[w][i_][q * 4 + 2] = sz2; s_sz[w][i_][q * 4 + 3] = sz3;

        float a0, a1, a2, a3;
        {
            const float* xr = &s_conv[h * 16 + q * 4];
            float4 xi = *reinterpret_cast<const float4*>(&xr[i_ * CONVP]);
            a0 = Dh * xi.x; a1 = Dh * xi.y; a2 = Dh * xi.z; a3 = Dh * xi.w;
            #pragma unroll
            for (int j = 0; j < 8; j++) {
                float4 xj = *reinterpret_cast<const float4*>(&xr[j * CONVP]);
                float s = sc[j];
                a0 += s * xj.x; a1 += s * xj.y; a2 += s * xj.z; a3 += s * xj.w;
            }
        }
        a0 *= sz0; a1 *= sz1; a2 *= sz2; a3 *= sz3;
        __syncwarp();

        // ---- part 2: S and G summaries ----
        float S0 = 0.f, S1 = 0.f, S2 = 0.f, S3 = 0.f;
        float G0 = 0.f, G1 = 0.f, G2 = 0.f, G3 = 0.f;
        #pragma unroll
        for (int k = 0; k < 8; k++) {
            float  xk  = s_conv[k * CONVP + h * 16 + p2];
            float  szk = s_sz[w][k][p2];
            float4 Bq  = *reinterpret_cast<const float4*>(&s_conv[k * CONVP + 512 + n0]);
            float4 Cq  = *reinterpret_cast<const float4*>(&s_conv[k * CONVP + 520 + n0]);
            float cx = coef[k] * xk;
            float es = e[k] * szk;
            S0 += cx * Bq.x; S1 += cx * Bq.y; S2 += cx * Bq.z; S3 += cx * Bq.w;
            G0 += es * Cq.x; G1 += es * Cq.y; G2 += es * Cq.z; G3 += es * Cq.w;
        }
        {
            size_t off = (size_t)((b * NHEADS + h) * NC + c) * 128 + lane * 4;
            ushort4 us; us.x = bf_enc(S0); us.y = bf_enc(S1); us.z = bf_enc(S2); us.w = bf_enc(S3);
            *reinterpret_cast<ushort4*>(&g_S[off]) = us;
            ushort4 ug; ug.x = bf_enc(G0); ug.y = bf_enc(G1); ug.z = bf_enc(G2); ug.w = bf_enc(G3);
            *reinterpret_cast<ushort4*>(&g_G[off]) = ug;
            if (lane == 0) g_d[(b * NHEADS + h) * NC + c] = e[7];
        }

        // reduce intra contribution over i-groups and accumulate
        #pragma unroll
        for (int off = 16; off >= 4; off >>= 1) {
            a0 += __shfl_down_sync(FULLM, a0, off);
            a1 += __shfl_down_sync(FULLM, a1, off);
            a2 += __shfl_down_sync(FULLM, a2, off);
            a3 += __shfl_down_sync(FULLM, a3, off);
        }
        if (lane < 4) {
            float* dst = &g_ybar[b * D_INNER + h * 16 + lane * 4];
            atomicAdd(dst + 0, a0); atomicAdd(dst + 1, a1);
            atomicAdd(dst + 2, a2); atomicAdd(dst + 3, a3);
        }
        __syncwarp();
    }
}

// ---------------- K5: B1 — per-segment final state + decay product ----------------
__global__ __launch_bounds__(128) void k_B1() {
    const int w = threadIdx.x >> 5, lane = threadIdx.x & 31;
    const int gw = blockIdx.x * 4 + w;
    const int b = gw >> 9, h = (gw >> 4) & 31, seg = gw & 15;
    const int bh = b * NHEADS + h;
    const size_t base = (size_t)(bh * NC + seg * CPS) * 128 + lane * 4;
    const float* dptr = &g_d[bh * NC + seg * CPS];
    float h0 = 0.f, h1 = 0.f, h2 = 0.f, h3 = 0.f, dp = 1.f;
    #pragma unroll 4
    for (int cc = 0; cc < CPS; cc++) {
        ushort4 us = *reinterpret_cast<const ushort4*>(&g_S[base + (size_t)cc * 128]);
        float d = dptr[cc];
        h0 = h0 * d + bf_dec(us.x); h1 = h1 * d + bf_dec(us.y);
        h2 = h2 * d + bf_dec(us.z); h3 = h3 * d + bf_dec(us.w);
        dp *= d;
    }
    *reinterpret_cast<float4*>(&g_Sfin[(size_t)(bh * NSEG + seg) * 128 + lane * 4]) =
        make_float4(h0, h1, h2, h3);
    if (lane == 0) g_Dseg[bh * NSEG + seg] = dp;
}

// ---------------- K6: combine segment states ----------------
__global__ void k_combine() {
    int tid = blockIdx.x * 128 + threadIdx.x;   // 65536 threads
    int bh = tid >> 7, pn = tid & 127;
    float H = 0.f;
    #pragma unroll
    for (int s = 0; s < NSEG; s++) {
        g_hin[(size_t)(bh * NSEG + s) * 128 + pn] = H;
        if (s < NSEG - 1)
            H = H * g_Dseg[bh * NSEG + s] + g_Sfin[(size_t)(bh * NSEG + s) * 128 + pn];
    }
}

// ---------------- K7: B3 — replay segments: acc += h . G, h = h*d + S ----------------
__global__ __launch_bounds__(128) void k_B3() {
    const int w = threadIdx.x >> 5, lane = threadIdx.x & 31;
    const int gw = blockIdx.x * 4 + w;
    const int b = gw >> 9, h = (gw >> 4) & 31, seg = gw & 15;
    const int bh = b * NHEADS + h;
    float4 hv = *reinterpret_cast<const float4*>(&g_hin[(size_t)(bh * NSEG + seg) * 128 + lane * 4]);
    float h0 = hv.x, h1 = hv.y, h2 = hv.z, h3 = hv.w;
    float accP = 0.f;
    const size_t base = (size_t)(bh * NC + seg * CPS) * 128 + lane * 4;
    const float* dptr = &g_d[bh * NC + seg * CPS];
    #pragma unroll 2
    for (int cc = 0; cc < CPS; cc++) {
        ushort4 uS = *reinterpret_cast<const ushort4*>(&g_S[base + (size_t)cc * 128]);
        ushort4 uG = *reinterpret_cast<const ushort4*>(&g_G[base + (size_t)cc * 128]);
        float d = dptr[cc];
        accP += h0 * bf_dec(uG.x) + h1 * bf_dec(uG.y) + h2 * bf_dec(uG.z) + h3 * bf_dec(uG.w);
        h0 = h0 * d + bf_dec(uS.x); h1 = h1 * d + bf_dec(uS.y);
        h2 = h2 * d + bf_dec(uS.z); h3 = h3 * d + bf_dec(uS.w);
    }
    accP += __shfl_xor_sync(FULLM, accP, 1);
    if (!(lane & 1)) atomicAdd(&g_ybar[b * D_INNER + h * 16 + (lane >> 1)], accP);
}

// ---------------- K8: pooled = (ybar/L) @ W_out^T; logits = pooled @ W_cls^T + b_cls ----------------
__global__ __launch_bounds__(256) void k_final(const float* __restrict__ Wout, const float* __restrict__ Wcls,
                                               const float* __restrict__ bcls, float* __restrict__ out) {
    __shared__ float sy[D_INNER];
    __shared__ float sp[D_MODEL];
    const int b = blockIdx.x, tid = threadIdx.x;
    sy[tid]       = g_ybar[b * D_INNER + tid];
    sy[tid + 256] = g_ybar[b * D_INNER + 256 + tid];
    __syncthreads();
    const int w = tid >> 5, lane = tid & 31;
    const int rsub = lane >> 3, sub = lane & 7;      // 4 rows / warp-iter, 8 lanes / row
    for (int it = 0; it < 8; it++) {
        int m = w * 32 + it * 4 + rsub;
        const float* wr = &Wout[(size_t)m * D_INNER];
        float s = 0.f;
        #pragma unroll
        for (int d0 = 0; d0 < D_INNER; d0 += 32) {
            float4 wv = *reinterpret_cast<const float4*>(&wr[d0 + sub * 4]);
            float4 yv = *reinterpret_cast<const float4*>(&sy[d0 + sub * 4]);
            s += wv.x * yv.x + wv.y * yv.y + wv.z * yv.z + wv.w * yv.w;
        }
        s += __shfl_down_sync(FULLM, s, 4);
        s += __shfl_down_sync(FULLM, s, 2);
        s += __shfl_down_sync(FULLM, s, 1);
        if (sub == 0) sp[m] = s * (1.f / SEQLEN);
    }
    __syncthreads();
    if (tid < OUT_SIZE) {
        float r = bcls[tid];
        #pragma unroll 8
        for (int k = 0; k < D_MODEL; k++) r += Wcls[tid * D_MODEL + k] * sp[k];
        out[b * OUT_SIZE + tid] = r;
    }
}

// ---------------- launch ----------------
extern "C" void kernel_launch(void* const* d_in, const int* in_sizes, int n_in,
                              void* d_out, int out_size) {
    const float* x    = (const float*)d_in[0];
    const float* Win  = (const float*)d_in[1];
    const float* bin  = (const float*)d_in[2];
    const float* Wip  = (const float*)d_in[3];
    const float* cw   = (const float*)d_in[4];
    const float* cb   = (const float*)d_in[5];
    const float* dtb  = (const float*)d_in[6];
    const float* Alog = (const float*)d_in[7];
    const float* Dp   = (const float*)d_in[8];
    const float* Wout = (const float*)d_in[9];
    const float* Wcls = (const float*)d_in[10];
    const float* bcls = (const float*)d_in[11];
    float* out = (float*)d_out;

    k_wcomb<<<243, 256>>>(Wip, Win, bin);
    dim3 g2(NTOK / 128, (D_INPROJ + 63) / 64);           // 512 x 17
    k_gemm<<<g2, 256>>>(x);
    k_zero<<<BATCH, D_INNER>>>();
    k_passA<<<BATCH * NC, 256>>>(cw, cb, dtb, Alog, Dp); // 8192 blocks
    k_B1<<<(BATCH * NHEADS * NSEG) / 4, 128>>>();
    k_combine<<<512, 128>>>();
    k_B3<<<(BATCH * NHEADS * NSEG) / 4, 128>>>();
    k_final<<<BATCH, D_MODEL>>>(Wout, Wcls, bcls, out);
}

// round 7
// speedup vs baseline: 1.5690x; 1.5690x over previous
#include <cuda_runtime.h>
#include <cuda_bf16.h>
#include <math.h>

// ---------------- problem constants ----------------
#define BATCH     16
#define SEQLEN    4096
#define INPUT_DIM 57
#define D_MODEL   256
#define D_INNER   512
#define D_STATE   8
#define HEADDIM   16
#define NHEADS    32
#define CHUNKSZ   8
#define CONV_DIM  528          // D_INNER + 2*D_STATE
#define D_INPROJ  1072         // 2*D_INNER + 2*D_STATE + NHEADS
#define NZB       1040         // bf16-stored cols (z | xBC); dt stored separately fp32
#define OUT_SIZE  6
#define NC        (SEQLEN/CHUNKSZ)   // 512 chunks per sequence
#define NSEG      16
#define CPS       (NC/NSEG)          // 32 chunks per segment
#define NTOK      (BATCH*SEQLEN)     // 65536
#define FULLM     0xffffffffu

// ---------------- scratch (device globals; no allocations) ----------------
__device__ __align__(16) float g_Wc  [D_INPROJ*INPUT_DIM];
__device__ __align__(16) float g_bias[D_INPROJ];
__device__ __align__(16) __nv_bfloat16 g_zx16[(size_t)NTOK*NZB];  // z | xBC, bf16
__device__ __align__(16) float g_dt  [NTOK*NHEADS];               // dt slice, fp32
__device__ __align__(16) __nv_bfloat16 g_S[(size_t)BATCH*NHEADS*NC*128]; // chunk state contribs
__device__ __align__(16) __nv_bfloat16 g_G[(size_t)BATCH*NHEADS*NC*128]; // chunk gated-C matrices
__device__ __align__(16) float g_d   [BATCH*NHEADS*NC];                  // chunk decays
__device__ __align__(16) float g_Sfin[BATCH*NHEADS*NSEG*HEADDIM*D_STATE];
__device__ __align__(16) float g_Dseg[BATCH*NHEADS*NSEG];
__device__ __align__(16) float g_hin [BATCH*NHEADS*NSEG*HEADDIM*D_STATE];
__device__ __align__(16) float g_ybar[BATCH*D_INNER];

// ---------------- helpers ----------------
__device__ __forceinline__ float siluf_fast(float x) {
    return x * __frcp_rn(1.f + __expf(-x));
}
__device__ __forceinline__ unsigned long long f2pack(float lo, float hi) {
    unsigned long long r;
    asm("mov.b64 %0, {%1,%2};" : "=l"(r) : "f"(lo), "f"(hi));
    return r;
}
__device__ __forceinline__ void f2unpack(unsigned long long v, float& lo, float& hi) {
    asm("mov.b64 {%0,%1}, %2;" : "=f"(lo), "=f"(hi) : "l"(v));
}
__device__ __forceinline__ unsigned long long ffma2(unsigned long long a, unsigned long long b, unsigned long long c) {
    unsigned long long d;
    asm("fma.rn.f32x2 %0, %1, %2, %3;" : "=l"(d) : "l"(a), "l"(b), "l"(c));
    return d;
}
__device__ __forceinline__ unsigned short bf_enc(float x) {
    return __bfloat16_as_ushort(__float2bfloat16_rn(x));
}
__device__ __forceinline__ float bf_dec(unsigned short u) {
    return __bfloat162float(__ushort_as_bfloat16(u));
}
__device__ __forceinline__ unsigned int bfpack2(float a, float b) {
    __nv_bfloat162 t;
    t.x = __float2bfloat16_rn(a);
    t.y = __float2bfloat16_rn(b);
    return *reinterpret_cast<unsigned int*>(&t);
}
__device__ __forceinline__ void bfunpack2(unsigned int u, float& a, float& b) {
    __nv_bfloat162 t = *reinterpret_cast<__nv_bfloat162*>(&u);
    a = __bfloat162float(t.x);
    b = __bfloat162float(t.y);
}

// ---------------- K1: W_comb = W_inproj @ W_in, bias = W_inproj @ b_in, + zero ybar ----------------
__global__ void k_wcomb(const float* __restrict__ Wip, const float* __restrict__ Win,
                        const float* __restrict__ bin) {
    int idx = blockIdx.x * 256 + threadIdx.x;
    if (idx < D_INPROJ * INPUT_DIM) {
        int r = idx / INPUT_DIM, k = idx % INPUT_DIM;
        float s = 0.f;
        #pragma unroll 8
        for (int m = 0; m < D_MODEL; m++) s += Wip[r * D_MODEL + m] * Win[m * INPUT_DIM + k];
        g_Wc[idx] = s;
    } else if (idx < D_INPROJ * INPUT_DIM + D_INPROJ) {
        int r = idx - D_INPROJ * INPUT_DIM;
        float s = 0.f;
        #pragma unroll 8
        for (int m = 0; m < D_MODEL; m++) s += Wip[r * D_MODEL + m] * bin[m];
        g_bias[r] = s;
    } else if (idx < D_INPROJ * INPUT_DIM + D_INPROJ + BATCH * D_INNER) {
        g_ybar[idx - (D_INPROJ * INPUT_DIM + D_INPROJ)] = 0.f;
    }
}

// ---------------- K2: zxbcdt = x @ W_comb^T + bias  (M=65536, N=1072, K=57) ----------------
// BM=128 rows, BN=64 cols, 256 threads, thread tile 8x4 (rows paired for f32x2).
// cols < 1040 stored bf16 to g_zx16; cols 1040..1071 (dt) stored fp32 to g_dt.
#define ASTRIDE 140
#define BSTRIDE 68
__global__ __launch_bounds__(256) void k_gemm(const float* __restrict__ x) {
    __shared__ __align__(16) float Ast[INPUT_DIM * ASTRIDE];  // [k][row]
    __shared__ __align__(16) float Bs [INPUT_DIM * BSTRIDE];  // [k][col]
    const int tid = threadIdx.x;
    const int tx = tid & 15, ty = tid >> 4;
    const int m0 = blockIdx.x * 128;
    const int n0 = blockIdx.y * 64;

    for (int idx = tid; idx < 128 * INPUT_DIM; idx += 256) {
        int r = idx / INPUT_DIM, k = idx - r * INPUT_DIM;
        Ast[k * ASTRIDE + r] = x[(size_t)(m0 + r) * INPUT_DIM + k];
    }
    for (int idx = tid; idx < 64 * INPUT_DIM; idx += 256) {
        int c = idx / INPUT_DIM, k = idx - c * INPUT_DIM;
        int col = n0 + c;
        Bs[k * BSTRIDE + c] = (col < D_INPROJ) ? g_Wc[col * INPUT_DIM + k] : 0.f;
    }
    __syncthreads();

    unsigned long long acc[4][4];   // [row-pair][col]
    #pragma unroll
    for (int rp = 0; rp < 4; rp++)
        #pragma unroll
        for (int c = 0; c < 4; c++) acc[rp][c] = 0ull;

    #pragma unroll 3
    for (int k = 0; k < INPUT_DIM; k++) {
        const float4 a03 = *reinterpret_cast<const float4*>(&Ast[k * ASTRIDE + ty * 8]);
        const float4 a47 = *reinterpret_cast<const float4*>(&Ast[k * ASTRIDE + ty * 8 + 4]);
        const float4 bv  = *reinterpret_cast<const float4*>(&Bs [k * BSTRIDE + tx * 4]);
        unsigned long long pa[4];
        pa[0] = f2pack(a03.x, a03.y); pa[1] = f2pack(a03.z, a03.w);
        pa[2] = f2pack(a47.x, a47.y); pa[3] = f2pack(a47.z, a47.w);
        unsigned long long bd[4];
        bd[0] = f2pack(bv.x, bv.x); bd[1] = f2pack(bv.y, bv.y);
        bd[2] = f2pack(bv.z, bv.z); bd[3] = f2pack(bv.w, bv.w);
        #pragma unroll
        for (int c = 0; c < 4; c++)
            #pragma unroll
            for (int rp = 0; rp < 4; rp++)
                acc[rp][c] = ffma2(pa[rp], bd[c], acc[rp][c]);
    }

    const int colbase = n0 + tx * 4;
    if (colbase < D_INPROJ) {
        const float4 bi = *reinterpret_cast<const float4*>(&g_bias[colbase]);
        #pragma unroll
        for (int rp = 0; rp < 4; rp++) {
            float l0, h0, l1, h1, l2, h2, l3, h3;
            f2unpack(acc[rp][0], l0, h0); f2unpack(acc[rp][1], l1, h1);
            f2unpack(acc[rp][2], l2, h2); f2unpack(acc[rp][3], l3, h3);
            l0 += bi.x; l1 += bi.y; l2 += bi.z; l3 += bi.w;
            h0 += bi.x; h1 += bi.y; h2 += bi.z; h3 += bi.w;
            const int r0 = m0 + ty * 8 + rp * 2;
            if (colbase < NZB) {
                uint2 u0; u0.x = bfpack2(l0, l1); u0.y = bfpack2(l2, l3);
                uint2 u1; u1.x = bfpack2(h0, h1); u1.y = bfpack2(h2, h3);
                *reinterpret_cast<uint2*>(&g_zx16[(size_t)r0 * NZB + colbase]) = u0;
                *reinterpret_cast<uint2*>(&g_zx16[(size_t)(r0 + 1) * NZB + colbase]) = u1;
            } else {
                const int dcol = colbase - NZB;   // 0..28, multiple of 4
                *reinterpret_cast<float4*>(&g_dt[(size_t)r0 * NHEADS + dcol]) =
                    make_float4(l0, l1, l2, l3);
                *reinterpret_cast<float4*>(&g_dt[(size_t)(r0 + 1) * NHEADS + dcol]) =
                    make_float4(h0, h1, h2, h3);
            }
        }
    }
}

// ---------------- K4: pass A — per-chunk: conv+silu, intra-gated output, S/G/d summaries ----------------
#define CONVP 532   // padded row stride for conv smem
__global__ __launch_bounds__(256) void k_passA(const float* __restrict__ cw, const float* __restrict__ cb,
                                               const float* __restrict__ dtb, const float* __restrict__ Alog,
                                               const float* __restrict__ Dp) {
    __shared__ __align__(16) float s_conv[8 * CONVP];   // conv+silu output: [token][channel]
    __shared__ float s_dt[8][33];                       // raw dt: [token][head]
    __shared__ float s_CB[64];                          // C_i . B_j (head-independent)
    __shared__ float s_sz[8][8][20];                    // silu(z): [warp][token][p]
    __shared__ float s_cA8[8][8], s_dtc8[8][8];         // per-warp chunk dt/cumA
    __shared__ float s_e[8][8], s_coef[8][8];           // per-warp exp tables
    __shared__ float s_sc[8][64];                       // per-warp score matrices
    __shared__ float s_A[32], s_Dh[32], s_dtb[32];

    const int tid = threadIdx.x, w = tid >> 5, lane = tid & 31;
    const int blk = blockIdx.x;
    const int b = blk >> 9, c = blk & 511;
    const int t0 = c * CHUNKSZ;
    const size_t row0 = (size_t)(b * SEQLEN + t0);

    if (tid < 32) {
        s_A[tid]   = -__expf(Alog[tid]);
        s_Dh[tid]  = Dp[tid];
        s_dtb[tid] = dtb[tid];
    }
    // dt tile (coalesced): 8 tokens x 32 heads
    {
        int j = tid >> 5, hh2 = tid & 31;
        s_dt[j][hh2] = g_dt[(row0 + j) * NHEADS + hh2];
    }

    // depthwise causal conv (width 4) + silu into smem (bf16 inputs)
    for (int ch = tid; ch < CONV_DIM; ch += 256) {
        const float w0 = cw[ch * 4], w1 = cw[ch * 4 + 1], w2 = cw[ch * 4 + 2], w3 = cw[ch * 4 + 3];
        const float bb = cb[ch];
        float v[11];
        #pragma unroll
        for (int tt = 0; tt < 11; tt++) {
            int t = t0 + tt - 3;
            v[tt] = (t >= 0) ? __bfloat162float(g_zx16[(size_t)(b * SEQLEN + t) * NZB + D_INNER + ch]) : 0.f;
        }
        #pragma unroll
        for (int u = 0; u < 8; u++) {
            float s = bb + w0 * v[u] + w1 * v[u + 1] + w2 * v[u + 2] + w3 * v[u + 3];
            s_conv[u * CONVP + ch] = siluf_fast(s);
        }
    }
    __syncthreads();

    // CB[i][j] = C_i . B_j  (shared across all 32 heads)
    if (tid < 64) {
        int i = tid >> 3, j = tid & 7;
        float s = 0.f;
        #pragma unroll
        for (int n = 0; n < 8; n++)
            s += s_conv[i * CONVP + 520 + n] * s_conv[j * CONVP + 512 + n];
        s_CB[tid] = s;
    }
    __syncthreads();

    const int i_ = lane >> 2, q = lane & 3;         // part-1 map
    const int p2 = lane >> 1, n0 = (lane & 1) * 4;  // part-2 map

    #pragma unroll 1
    for (int hh = 0; hh < 4; hh++) {
        const int h = w * 4 + hh;
        const float Dh = s_Dh[h];

        // dtc + cumulative A on lanes 0..7; publish to smem
        {
            float dtc_l = 0.f;
            if (lane < 8) {
                float xv = s_dt[lane][h] + s_dtb[h];
                dtc_l = (xv > 20.f) ? xv : __logf(1.f + __expf(xv));
            }
            float cs = dtc_l;
            #pragma unroll
            for (int off = 1; off < 8; off <<= 1) {
                float vv = __shfl_up_sync(FULLM, cs, off);
                if (lane >= off) cs += vv;
            }
            if (lane < 8) {
                s_dtc8[w][lane] = dtc_l;
                s_cA8[w][lane]  = cs * s_A[h];
            }
        }
        __syncwarp();

        // cooperative exp tables: e, coef (8 each), sc (64), computed once per warp
        {
            const float cA7 = s_cA8[w][7];
            int j8 = lane & 7;
            float caj = s_cA8[w][j8], dtj = s_dtc8[w][j8];
            if (lane < 8)       s_e[w][j8]    = __expf(caj);
            else if (lane < 16) s_coef[w][j8] = __expf(cA7 - caj) * dtj;
            #pragma unroll
            for (int t = lane; t < 64; t += 32) {
                int si = t >> 3, sj = t & 7;
                float v = 0.f;
                if (sj <= si)
                    v = s_CB[t] * __expf(s_cA8[w][si] - s_cA8[w][sj]) * s_dtc8[w][sj];
                s_sc[w][t] = v;
            }
        }
        __syncwarp();

        // ---- part 1: intra + D term, gated ----
        float sc_r[8];
        #pragma unroll
        for (int j = 0; j < 8; j++) sc_r[j] = s_sc[w][i_ * 8 + j];

        uint2 zu = *reinterpret_cast<const uint2*>(&g_zx16[(row0 + i_) * NZB + h * 16 + q * 4]);
        float z0, z1, z2, z3;
        bfunpack2(zu.x, z0, z1);
        bfunpack2(zu.y, z2, z3);
        float sz0 = siluf_fast(z0), sz1 = siluf_fast(z1), sz2 = siluf_fast(z2), sz3 = siluf_fast(z3);
        s_sz[w][i_][q * 4 + 0] = sz0; s_sz[w][i_][q * 4 + 1] = sz1;
        s_sz[w][i_][q * 4 + 2] = sz2; s_sz[w][i_][q * 4 + 3] = sz3;

        float a0, a1, a2, a3;
        {
            const float* xr = &s_conv[h * 16 + q * 4];
            float4 xi = *reinterpret_cast<const float4*>(&xr[i_ * CONVP]);
            a0 = Dh * xi.x; a1 = Dh * xi.y; a2 = Dh * xi.z; a3 = Dh * xi.w;
            #pragma unroll
            for (int j = 0; j < 8; j++) {
                float4 xj = *reinterpret_cast<const float4*>(&xr[j * CONVP]);
                float s = sc_r[j];
                a0 += s * xj.x; a1 += s * xj.y; a2 += s * xj.z; a3 += s * xj.w;
            }
        }
        a0 *= sz0; a1 *= sz1; a2 *= sz2; a3 *= sz3;
        __syncwarp();

        // ---- part 2: S and G summaries ----
        float S0 = 0.f, S1 = 0.f, S2 = 0.f, S3 = 0.f;
        float G0 = 0.f, G1 = 0.f, G2 = 0.f, G3 = 0.f;
        #pragma unroll
        for (int k = 0; k < 8; k++) {
            float  xk  = s_conv[k * CONVP + h * 16 + p2];
            float  szk = s_sz[w][k][p2];
            float4 Bq  = *reinterpret_cast<const float4*>(&s_conv[k * CONVP + 512 + n0]);
            float4 Cq  = *reinterpret_cast<const float4*>(&s_conv[k * CONVP + 520 + n0]);
            float cx = s_coef[w][k] * xk;
            float es = s_e[w][k] * szk;
            S0 += cx * Bq.x; S1 += cx * Bq.y; S2 += cx * Bq.z; S3 += cx * Bq.w;
            G0 += es * Cq.x; G1 += es * Cq.y; G2 += es * Cq.z; G3 += es * Cq.w;
        }
        {
            size_t off = (size_t)((b * NHEADS + h) * NC + c) * 128 + lane * 4;
            ushort4 us; us.x = bf_enc(S0); us.y = bf_enc(S1); us.z = bf_enc(S2); us.w = bf_enc(S3);
            *reinterpret_cast<ushort4*>(&g_S[off]) = us;
            ushort4 ug; ug.x = bf_enc(G0); ug.y = bf_enc(G1); ug.z = bf_enc(G2); ug.w = bf_enc(G3);
            *reinterpret_cast<ushort4*>(&g_G[off]) = ug;
            if (lane == 0) g_d[(b * NHEADS + h) * NC + c] = s_e[w][7];
        }

        // reduce intra contribution over i-groups and accumulate
        #pragma unroll
        for (int off = 16; off >= 4; off >>= 1) {
            a0 += __shfl_down_sync(FULLM, a0, off);
            a1 += __shfl_down_sync(FULLM, a1, off);
            a2 += __shfl_down_sync(FULLM, a2, off);
            a3 += __shfl_down_sync(FULLM, a3, off);
        }
        if (lane < 4) {
            float* dst = &g_ybar[b * D_INNER + h * 16 + lane * 4];
            atomicAdd(dst + 0, a0); atomicAdd(dst + 1, a1);
            atomicAdd(dst + 2, a2); atomicAdd(dst + 3, a3);
        }
        __syncwarp();
    }
}

// ---------------- K5: B1 — per-segment final state + decay product ----------------
__global__ __launch_bounds__(128) void k_B1() {
    const int w = threadIdx.x >> 5, lane = threadIdx.x & 31;
    const int gw = blockIdx.x * 4 + w;
    const int b = gw >> 9, h = (gw >> 4) & 31, seg = gw & 15;
    const int bh = b * NHEADS + h;
    const size_t base = (size_t)(bh * NC + seg * CPS) * 128 + lane * 4;
    const float* dptr = &g_d[bh * NC + seg * CPS];
    float h0 = 0.f, h1 = 0.f, h2 = 0.f, h3 = 0.f, dp = 1.f;
    #pragma unroll 4
    for (int cc = 0; cc < CPS; cc++) {
        ushort4 us = *reinterpret_cast<const ushort4*>(&g_S[base + (size_t)cc * 128]);
        float d = dptr[cc];
        h0 = h0 * d + bf_dec(us.x); h1 = h1 * d + bf_dec(us.y);
        h2 = h2 * d + bf_dec(us.z); h3 = h3 * d + bf_dec(us.w);
        dp *= d;
    }
    *reinterpret_cast<float4*>(&g_Sfin[(size_t)(bh * NSEG + seg) * 128 + lane * 4]) =
        make_float4(h0, h1, h2, h3);
    if (lane == 0) g_Dseg[bh * NSEG + seg] = dp;
}

// ---------------- K6: combine segment states ----------------
__global__ void k_combine() {
    int tid = blockIdx.x * 128 + threadIdx.x;   // 65536 threads
    int bh = tid >> 7, pn = tid & 127;
    float H = 0.f;
    #pragma unroll
    for (int s = 0; s < NSEG; s++) {
        g_hin[(size_t)(bh * NSEG + s) * 128 + pn] = H;
        if (s < NSEG - 1)
            H = H * g_Dseg[bh * NSEG + s] + g_Sfin[(size_t)(bh * NSEG + s) * 128 + pn];
    }
}

// ---------------- K7: B3 — replay segments: acc += h . G, h = h*d + S ----------------
__global__ __launch_bounds__(128) void k_B3() {
    const int w = threadIdx.x >> 5, lane = threadIdx.x & 31;
    const int gw = blockIdx.x * 4 + w;
    const int b = gw >> 9, h = (gw >> 4) & 31, seg = gw & 15;
    const int bh = b * NHEADS + h;
    float4 hv = *reinterpret_cast<const float4*>(&g_hin[(size_t)(bh * NSEG + seg) * 128 + lane * 4]);
    float h0 = hv.x, h1 = hv.y, h2 = hv.z, h3 = hv.w;
    float accP = 0.f;
    const size_t base = (size_t)(bh * NC + seg * CPS) * 128 + lane * 4;
    const float* dptr = &g_d[bh * NC + seg * CPS];
    #pragma unroll 2
    for (int cc = 0; cc < CPS; cc++) {
        ushort4 uS = *reinterpret_cast<const ushort4*>(&g_S[base + (size_t)cc * 128]);
        ushort4 uG = *reinterpret_cast<const ushort4*>(&g_G[base + (size_t)cc * 128]);
        float d = dptr[cc];
        accP += h0 * bf_dec(uG.x) + h1 * bf_dec(uG.y) + h2 * bf_dec(uG.z) + h3 * bf_dec(uG.w);
        h0 = h0 * d + bf_dec(uS.x); h1 = h1 * d + bf_dec(uS.y);
        h2 = h2 * d + bf_dec(uS.z); h3 = h3 * d + bf_dec(uS.w);
    }
    accP += __shfl_xor_sync(FULLM, accP, 1);
    if (!(lane & 1)) atomicAdd(&g_ybar[b * D_INNER + h * 16 + (lane >> 1)], accP);
}

// ---------------- K8: pooled = (ybar/L) @ W_out^T; logits = pooled @ W_cls^T + b_cls ----------------
__global__ __launch_bounds__(256) void k_final(const float* __restrict__ Wout, const float* __restrict__ Wcls,
                                               const float* __restrict__ bcls, float* __restrict__ out) {
    __shared__ float sy[D_INNER];
    __shared__ float sp[D_MODEL];
    const int b = blockIdx.x, tid = threadIdx.x;
    sy[tid]       = g_ybar[b * D_INNER + tid];
    sy[tid + 256] = g_ybar[b * D_INNER + 256 + tid];
    __syncthreads();
    const int w = tid >> 5, lane = tid & 31;
    const int rsub = lane >> 3, sub = lane & 7;
    for (int it = 0; it < 8; it++) {
        int m = w * 32 + it * 4 + rsub;
        const float* wr = &Wout[(size_t)m * D_INNER];
        float s = 0.f;
        #pragma unroll
        for (int d0 = 0; d0 < D_INNER; d0 += 32) {
            float4 wv = *reinterpret_cast<const float4*>(&wr[d0 + sub * 4]);
            float4 yv = *reinterpret_cast<const float4*>(&sy[d0 + sub * 4]);
            s += wv.x * yv.x + wv.y * yv.y + wv.z * yv.z + wv.w * yv.w;
        }
        s += __shfl_down_sync(FULLM, s, 4);
        s += __shfl_down_sync(FULLM, s, 2);
        s += __shfl_down_sync(FULLM, s, 1);
        if (sub == 0) sp[m] = s * (1.f / SEQLEN);
    }
    __syncthreads();
    if (tid < OUT_SIZE) {
        float r = bcls[tid];
        #pragma unroll 8
        for (int k = 0; k < D_MODEL; k++) r += Wcls[tid * D_MODEL + k] * sp[k];
        out[b * OUT_SIZE + tid] = r;
    }
}

// ---------------- launch ----------------
extern "C" void kernel_launch(void* const* d_in, const int* in_sizes, int n_in,
                              void* d_out, int out_size) {
    const float* x    = (const float*)d_in[0];
    const float* Win  = (const float*)d_in[1];
    const float* bin  = (const float*)d_in[2];
    const float* Wip  = (const float*)d_in[3];
    const float* cw   = (const float*)d_in[4];
    const float* cb   = (const float*)d_in[5];
    const float* dtb  = (const float*)d_in[6];
    const float* Alog = (const float*)d_in[7];
    const float* Dp   = (const float*)d_in[8];
    const float* Wout = (const float*)d_in[9];
    const float* Wcls = (const float*)d_in[10];
    const float* bcls = (const float*)d_in[11];
    float* out = (float*)d_out;

    k_wcomb<<<275, 256>>>(Wip, Win, bin);                // also zeros g_ybar
    dim3 g2(NTOK / 128, (D_INPROJ + 63) / 64);           // 512 x 17
    k_gemm<<<g2, 256>>>(x);
    k_passA<<<BATCH * NC, 256>>>(cw, cb, dtb, Alog, Dp); // 8192 blocks
    k_B1<<<(BATCH * NHEADS * NSEG) / 4, 128>>>();
    k_combine<<<512, 128>>>();
    k_B3<<<(BATCH * NHEADS * NSEG) / 4, 128>>>();
    k_final<<<BATCH, D_MODEL>>>(Wout, Wcls, bcls, out);
}